// round 12
// baseline (speedup 1.0000x reference)
#include <cuda_runtime.h>
#include <cuda_bf16.h>
#include <cuda_fp16.h>
#include <cstdint>
#include <cstddef>

#define N_NODES 100000
#define N_EDGES 600000
#define D 128
#define BN_EPS 1e-5f

// ---------------- scratch (static device globals; no allocation) ----------------
__device__ __half2 g_acc_o[(size_t)N_NODES * 64];   // fp16 sums of (h_src - e) at dst
__device__ __half2 g_acc_i[(size_t)N_NODES * 64];   // fp16 sums of (h_dst - e) at src
__device__ __half2 g_node16[(size_t)N_NODES * 64];  // fp16 copy of node_embs
__device__ float  g_cnt[2 * N_NODES];               // [0:N) in-deg(dst), [N:2N) deg at src
// B fragments (fp16, hi only): [kstep 0..23][ntile 0..15][lane 0..31] = (b0,b1)
__device__ uint2  g_Bfrag[24 * 16 * 32];
__device__ float  g_bias[D];
__device__ double g_sum[D];
__device__ double g_sumsq[D];

// ---------------- helpers ----------------
__device__ __forceinline__ void red_add_h2v4(__half2* p, __half2 a, __half2 b,
                                             __half2 c, __half2 d) {
    asm volatile("red.global.add.noftz.v4.f16x2 [%0], {%1,%2,%3,%4};"
                 :: "l"(p),
                    "r"(*reinterpret_cast<uint32_t*>(&a)),
                    "r"(*reinterpret_cast<uint32_t*>(&b)),
                    "r"(*reinterpret_cast<uint32_t*>(&c)),
                    "r"(*reinterpret_cast<uint32_t*>(&d)) : "memory");
}

__device__ __forceinline__ void mma_fp16(float* d, uint32_t a0, uint32_t a1, uint32_t a2,
                                         uint32_t a3, uint32_t b0, uint32_t b1) {
    asm volatile(
        "mma.sync.aligned.m16n8k16.row.col.f32.f16.f16.f32 "
        "{%0,%1,%2,%3}, {%4,%5,%6,%7}, {%8,%9}, {%0,%1,%2,%3};"
        : "+f"(d[0]), "+f"(d[1]), "+f"(d[2]), "+f"(d[3])
        : "r"(a0), "r"(a1), "r"(a2), "r"(a3), "r"(b0), "r"(b1));
}

__device__ __forceinline__ uint32_t hscale(uint32_t u, __half2 s) {
    __half2 v = *reinterpret_cast<__half2*>(&u);
    v = __hmul2(v, s);
    return *reinterpret_cast<uint32_t*>(&v);
}

// ---------------- K0: zero scratch + fp16 node table + pack W + bias ----------------
__global__ void k_init(const float* __restrict__ node,
                       const float* __restrict__ WO, const float* __restrict__ WI,
                       const float* __restrict__ WS, const float* __restrict__ bO,
                       const float* __restrict__ bI, const float* __restrict__ bS) {
    size_t idx = (size_t)blockIdx.x * blockDim.x + threadIdx.x;
    size_t stride = (size_t)gridDim.x * blockDim.x;
    const size_t n4 = (size_t)N_NODES * 16;
    uint4 z = make_uint4(0, 0, 0, 0);
    uint4* ao = reinterpret_cast<uint4*>(g_acc_o);
    uint4* ai = reinterpret_cast<uint4*>(g_acc_i);
    for (size_t i = idx; i < n4; i += stride) { ao[i] = z; ai[i] = z; }
    // node fp32 -> fp16 table (float4 loads, uint2 stores)
    const float4* nsrc = reinterpret_cast<const float4*>(node);
    uint2* ndst = reinterpret_cast<uint2*>(g_node16);
    const size_t nq = (size_t)N_NODES * 32;
    for (size_t i = idx; i < nq; i += stride) {
        float4 v = __ldg(&nsrc[i]);
        __half2 a = __floats2half2_rn(v.x, v.y);
        __half2 b = __floats2half2_rn(v.z, v.w);
        ndst[i] = make_uint2(*reinterpret_cast<uint32_t*>(&a),
                             *reinterpret_cast<uint32_t*>(&b));
    }
    float4 zf = make_float4(0.f, 0.f, 0.f, 0.f);
    float4* cp = reinterpret_cast<float4*>(g_cnt);
    for (size_t i = idx; i < (2 * N_NODES) / 4; i += stride) cp[i] = zf;
    if (idx < D) { g_sum[idx] = 0.0; g_sumsq[idx] = 0.0; g_bias[idx] = bO[idx] + bI[idx] + bS[idx]; }
    if (idx < 24 * 16 * 32) {
        int t  = (int)idx >> 9;
        int nt = ((int)idx >> 5) & 15;
        int l  = (int)idx & 31;
        int n  = nt * 8 + (l >> 2);
        int kg = t * 16 + (l & 3) * 2;
        const float* Wsrc = (kg < 128) ? WO : ((kg < 256) ? WI : WS);
        int kk = kg & 127;
        float w00 = __ldg(&Wsrc[n * 128 + kk]);
        float w01 = __ldg(&Wsrc[n * 128 + kk + 1]);
        float w10 = __ldg(&Wsrc[n * 128 + kk + 8]);
        float w11 = __ldg(&Wsrc[n * 128 + kk + 9]);
        __half2 b0 = __floats2half2_rn(w00, w01);
        __half2 b1 = __floats2half2_rn(w10, w11);
        g_Bfrag[idx] = make_uint2(*reinterpret_cast<uint32_t*>(&b0),
                                  *reinterpret_cast<uint32_t*>(&b1));
    }
}

// ---------------- K1: edge scatter (fp16 node reads, direct edge loads) ----------------
__global__ __launch_bounds__(256) void k_scatter(const float* __restrict__ edge,
                                                 const int* __restrict__ src,
                                                 const int* __restrict__ dst) {
    int e = blockIdx.x * 8 + (threadIdx.x >> 5);
    if (e >= N_EDGES) return;
    int lane = threadIdx.x & 31;
    int half = lane >> 4;
    int i = lane & 15;
    int s = __ldg(&src[e]);
    int d = __ldg(&dst[e]);
    const float4* ep = reinterpret_cast<const float4*>(edge) + (size_t)e * 32;
    float4 eA = __ldcs(&ep[2 * i]);
    float4 eB = __ldcs(&ep[2 * i + 1]);
    int nrow = half ? d : s;
    const uint4* n16 = reinterpret_cast<const uint4*>(g_node16);
    uint4 nv = __ldg(&n16[(size_t)nrow * 16 + i]);   // elements 8i..8i+7 as 4x half2
    float2 f0 = __half22float2(*reinterpret_cast<__half2*>(&nv.x));
    float2 f1 = __half22float2(*reinterpret_cast<__half2*>(&nv.y));
    float2 f2 = __half22float2(*reinterpret_cast<__half2*>(&nv.z));
    float2 f3 = __half22float2(*reinterpret_cast<__half2*>(&nv.w));
    __half2 m0 = __floats2half2_rn(f0.x - eA.x, f0.y - eA.y);
    __half2 m1 = __floats2half2_rn(f1.x - eA.z, f1.y - eA.w);
    __half2 m2 = __floats2half2_rn(f2.x - eB.x, f2.y - eB.y);
    __half2 m3 = __floats2half2_rn(f3.x - eB.z, f3.y - eB.w);
    __half2* base = half ? (g_acc_i + (size_t)s * 64) : (g_acc_o + (size_t)d * 64);
    red_add_h2v4(base + i * 4, m0, m1, m2, m3);
    if (lane == 0)  atomicAdd(&g_cnt[d], 1.f);
    if (lane == 16) atomicAdd(&g_cnt[N_NODES + s], 1.f);
}

// ---------------- K2: fp16 HMMA GEMM, 2-kstep cp.async stages ----------------
// CTA: 128 rows x 128 cols, 8 warps = 4 (rows, wy) x 2 (cols, wx), warp tile 32x64.
#define NSTAGE 4
#define ROW_B 80                       // 64B data + 16B pad (conflict-free ldmatrix)
#define STG_BYTES (128 * ROW_B)

__global__ __launch_bounds__(256, 2) void k_gemm(float* __restrict__ out) {
    __shared__ __align__(16) unsigned char sA[NSTAGE][STG_BYTES];
    __shared__ float s_inv[2 * 128];
    __shared__ float s_red[2 * 128];

    int tid = threadIdx.x;
    int l = tid & 31;
    int w = tid >> 5;
    int wy = w & 3;           // row group
    int wx = w >> 2;          // col group
    int row0 = blockIdx.x * 128;

    uint32_t sA_base = (uint32_t)__cvta_generic_to_shared(&sA[0][0]);

    {
        int i = tid & 127;
        int r = row0 + i;
        float v = 0.f;
        if (r < N_NODES) v = 1.f / fmaxf(g_cnt[(tid < 128 ? 0 : N_NODES) + r], 1.f);
        s_inv[tid] = v;
        if (tid < 128) { s_red[tid] = 0.f; s_red[128 + tid] = 0.f; }
    }

    int crow = tid >> 1;
    int chalf = tid & 1;
    int cgrow = row0 + crow;
    int cvalid = (cgrow < N_NODES) ? 16 : 0;
    uint32_t cdst = crow * ROW_B + chalf * 32;

#define ISSUE_STAGE(st)                                                                  \
    do {                                                                                 \
        if ((st) < 12) {                                                                 \
            const char* _b = ((st) < 4) ? (const char*)g_acc_o                           \
                           : ((st) < 8) ? (const char*)g_acc_i : (const char*)g_node16;  \
            const char* _g = _b + (size_t)cgrow * 256 + ((st) & 3) * 64 + chalf * 32;    \
            uint32_t _s = sA_base + ((st) & (NSTAGE - 1)) * STG_BYTES + cdst;            \
            asm volatile("cp.async.cg.shared.global [%0], [%1], 16, %2;"                 \
                         :: "r"(_s), "l"(_g), "r"(cvalid));                              \
            asm volatile("cp.async.cg.shared.global [%0], [%1], 16, %2;"                 \
                         :: "r"(_s + 16), "l"(_g + 16), "r"(cvalid));                    \
        }                                                                                \
        asm volatile("cp.async.commit_group;");                                          \
    } while (0)

    ISSUE_STAGE(0);
    ISSUE_STAGE(1);
    ISSUE_STAGE(2);
    __syncthreads();   // s_inv/s_red ready

    float acc[2][8][4];
#pragma unroll
    for (int mt = 0; mt < 2; mt++)
#pragma unroll
        for (int nt = 0; nt < 8; nt++)
#pragma unroll
            for (int q = 0; q < 4; q++) acc[mt][nt][q] = 0.f;

    const int lq = l >> 2;
    const int lk = (l & 3) * 2;

    __half2 sco[2][2], sci[2][2];
#pragma unroll
    for (int mt = 0; mt < 2; mt++) {
        int rbase = wy * 32 + mt * 16 + lq;
        sco[mt][0] = __float2half2_rn(s_inv[rbase]);
        sco[mt][1] = __float2half2_rn(s_inv[rbase + 8]);
        sci[mt][0] = __float2half2_rn(s_inv[128 + rbase]);
        sci[mt][1] = __float2half2_rn(s_inv[128 + rbase + 8]);
    }

    for (int st = 0; st < 12; st++) {
        asm volatile("cp.async.wait_group %0;" :: "n"(2));
        __syncthreads();

        uint32_t stg = sA_base + (st & (NSTAGE - 1)) * STG_BYTES;
        uint32_t A[2][2][4];    // [sub][mt][frag]
#pragma unroll
        for (int sub = 0; sub < 2; sub++) {
#pragma unroll
            for (int mt = 0; mt < 2; mt++) {
                int trow = wy * 32 + mt * 16 + (l & 15);
                uint32_t addr = stg + trow * ROW_B + sub * 32 + (l >> 4) * 16;
                asm volatile("ldmatrix.sync.aligned.m8n8.x4.shared.b16 {%0,%1,%2,%3}, [%4];"
                             : "=r"(A[sub][mt][0]), "=r"(A[sub][mt][1]),
                               "=r"(A[sub][mt][2]), "=r"(A[sub][mt][3])
                             : "r"(addr));
                if (st < 8) {
                    const __half2* sc = (st < 4) ? sco[mt] : sci[mt];
                    A[sub][mt][0] = hscale(A[sub][mt][0], sc[0]);
                    A[sub][mt][1] = hscale(A[sub][mt][1], sc[1]);
                    A[sub][mt][2] = hscale(A[sub][mt][2], sc[0]);
                    A[sub][mt][3] = hscale(A[sub][mt][3], sc[1]);
                }
            }
        }
        ISSUE_STAGE(st + 3);

#pragma unroll
        for (int sub = 0; sub < 2; sub++) {
            int t = st * 2 + sub;
            const uint2* gBt = g_Bfrag + (t * 16 + wx * 8) * 32 + l;
#pragma unroll
            for (int nt = 0; nt < 8; nt++) {
                uint2 B = __ldg(&gBt[nt * 32]);
#pragma unroll
                for (int mt = 0; mt < 2; mt++) {
                    mma_fp16(acc[mt][nt], A[sub][mt][0], A[sub][mt][1],
                             A[sub][mt][2], A[sub][mt][3], B.x, B.y);
                }
            }
        }
    }

    // ---- epilogue: h = (acc + bias)/3, store, BN partial stats ----
    const float third = 1.f / 3.f;
    const float2* bias2 = reinterpret_cast<const float2*>(g_bias);
    float2* o2 = reinterpret_cast<float2*>(out);
    float ps[16], pq[16];
#pragma unroll
    for (int j = 0; j < 16; j++) { ps[j] = 0.f; pq[j] = 0.f; }

#pragma unroll
    for (int mt = 0; mt < 2; mt++) {
        int ra = row0 + wy * 32 + mt * 16 + lq;
        int rb = ra + 8;
#pragma unroll
        for (int nt = 0; nt < 8; nt++) {
            int col = wx * 64 + nt * 8 + lk;
            float2 bv = __ldg(&bias2[col >> 1]);
            if (ra < N_NODES) {
                float2 h0;
                h0.x = (acc[mt][nt][0] + bv.x) * third;
                h0.y = (acc[mt][nt][1] + bv.y) * third;
                o2[(size_t)ra * 64 + (col >> 1)] = h0;
                ps[nt * 2 + 0] += h0.x; pq[nt * 2 + 0] += h0.x * h0.x;
                ps[nt * 2 + 1] += h0.y; pq[nt * 2 + 1] += h0.y * h0.y;
            }
            if (rb < N_NODES) {
                float2 h1;
                h1.x = (acc[mt][nt][2] + bv.x) * third;
                h1.y = (acc[mt][nt][3] + bv.y) * third;
                o2[(size_t)rb * 64 + (col >> 1)] = h1;
                ps[nt * 2 + 0] += h1.x; pq[nt * 2 + 0] += h1.x * h1.x;
                ps[nt * 2 + 1] += h1.y; pq[nt * 2 + 1] += h1.y * h1.y;
            }
        }
    }
#pragma unroll
    for (int j = 0; j < 16; j++) {
        ps[j] += __shfl_xor_sync(0xFFFFFFFFu, ps[j], 4);
        ps[j] += __shfl_xor_sync(0xFFFFFFFFu, ps[j], 8);
        ps[j] += __shfl_xor_sync(0xFFFFFFFFu, ps[j], 16);
        pq[j] += __shfl_xor_sync(0xFFFFFFFFu, pq[j], 4);
        pq[j] += __shfl_xor_sync(0xFFFFFFFFu, pq[j], 8);
        pq[j] += __shfl_xor_sync(0xFFFFFFFFu, pq[j], 16);
    }
    if (l < 4) {
#pragma unroll
        for (int j = 0; j < 16; j++) {
            int col = wx * 64 + (j >> 1) * 8 + l * 2 + (j & 1);
            atomicAdd(&s_red[col], ps[j]);
            atomicAdd(&s_red[128 + col], pq[j]);
        }
    }
    __syncthreads();
    if (tid < 128) atomicAdd(&g_sum[tid], (double)s_red[tid]);
    else           atomicAdd(&g_sumsq[tid - 128], (double)s_red[tid]);
}

// ---------------- K3: BN finalize + in-place normalize (fused, exact mapping) ----------------
// 6250 blocks x 256 threads; each thread handles float4 i and i + 1,600,000
// (1.6M % 32 == 0 -> same column group, shared scale/shift registers).
#define BN_HALF 1600000u

__global__ __launch_bounds__(256) void k_bn(float* __restrict__ out,
                                            const float* __restrict__ gamma,
                                            const float* __restrict__ beta) {
    __shared__ float s_aff[2 * D];
    int tid = threadIdx.x;
    if (tid < D) {
        double mu = g_sum[tid] / (double)N_NODES;
        double var = g_sumsq[tid] / (double)N_NODES - mu * mu;
        float sc = __ldg(&gamma[tid]) * rsqrtf((float)var + BN_EPS);
        s_aff[tid] = sc;
        s_aff[D + tid] = __ldg(&beta[tid]) - (float)mu * sc;
    }
    __syncthreads();
    size_t i = (size_t)blockIdx.x * 256 + tid;
    float4* o4 = reinterpret_cast<float4*>(out);
    const float4* sc4 = reinterpret_cast<const float4*>(s_aff);
    const float4* sh4 = reinterpret_cast<const float4*>(s_aff + D);
    float4 sc = sc4[i & 31];
    float4 sh = sh4[i & 31];
    float4 v0 = o4[i];
    float4 v1 = o4[i + BN_HALF];
    v0.x = fmaf(v0.x, sc.x, sh.x);
    v0.y = fmaf(v0.y, sc.y, sh.y);
    v0.z = fmaf(v0.z, sc.z, sh.z);
    v0.w = fmaf(v0.w, sc.w, sh.w);
    v1.x = fmaf(v1.x, sc.x, sh.x);
    v1.y = fmaf(v1.y, sc.y, sh.y);
    v1.z = fmaf(v1.z, sc.z, sh.z);
    v1.w = fmaf(v1.w, sc.w, sh.w);
    o4[i] = v0;
    o4[i + BN_HALF] = v1;
}

// ---------------- launch ----------------
extern "C" void kernel_launch(void* const* d_in, const int* in_sizes, int n_in,
                              void* d_out, int out_size) {
    const float* node  = (const float*)d_in[0];
    const float* edge  = (const float*)d_in[1];
    const float* WO    = (const float*)d_in[2];
    const float* bO    = (const float*)d_in[3];
    const float* WI    = (const float*)d_in[4];
    const float* bI    = (const float*)d_in[5];
    const float* WS    = (const float*)d_in[6];
    const float* bS    = (const float*)d_in[7];
    const float* gamma = (const float*)d_in[8];
    const float* beta  = (const float*)d_in[9];
    const int*   src   = (const int*)d_in[10];
    const int*   dst   = (const int*)d_in[11];
    float* out = (float*)d_out;

    k_init<<<1184, 256>>>(node, WO, WI, WS, bO, bI, bS);
    k_scatter<<<N_EDGES / 8, 256>>>(edge, src, dst);
    k_gemm<<<(N_NODES + 127) / 128, 256>>>(out);
    k_bn<<<6250, 256>>>(out, gamma, beta);
}

// round 13
// speedup vs baseline: 1.0649x; 1.0649x over previous
#include <cuda_runtime.h>
#include <cuda_bf16.h>
#include <cuda_fp16.h>
#include <cstdint>
#include <cstddef>

#define N_NODES 100000
#define N_EDGES 600000
#define D 128
#define BN_EPS 1e-5f

// ---------------- scratch (static device globals; no allocation) ----------------
__device__ __half2 g_acc_o[(size_t)N_NODES * 64];   // fp16 sums of (h_src - e) at dst
__device__ __half2 g_acc_i[(size_t)N_NODES * 64];   // fp16 sums of (h_dst - e) at src
__device__ __half2 g_node16[(size_t)N_NODES * 64];  // fp16 copy of node_embs
__device__ float  g_cnt[2 * N_NODES];               // [0:N) in-deg(dst), [N:2N) deg at src
// B fragments (fp16, hi only): [kstep 0..23][ntile 0..15][lane 0..31] = (b0,b1)
__device__ uint2  g_Bfrag[24 * 16 * 32];
__device__ float  g_bias[D];
__device__ double g_sum[D];
__device__ double g_sumsq[D];

// ---------------- helpers ----------------
__device__ __forceinline__ void red_add_h2v4(__half2* p, __half2 a, __half2 b,
                                             __half2 c, __half2 d) {
    asm volatile("red.global.add.noftz.v4.f16x2 [%0], {%1,%2,%3,%4};"
                 :: "l"(p),
                    "r"(*reinterpret_cast<uint32_t*>(&a)),
                    "r"(*reinterpret_cast<uint32_t*>(&b)),
                    "r"(*reinterpret_cast<uint32_t*>(&c)),
                    "r"(*reinterpret_cast<uint32_t*>(&d)) : "memory");
}

__device__ __forceinline__ void mma_fp16(float* d, uint32_t a0, uint32_t a1, uint32_t a2,
                                         uint32_t a3, uint32_t b0, uint32_t b1) {
    asm volatile(
        "mma.sync.aligned.m16n8k16.row.col.f32.f16.f16.f32 "
        "{%0,%1,%2,%3}, {%4,%5,%6,%7}, {%8,%9}, {%0,%1,%2,%3};"
        : "+f"(d[0]), "+f"(d[1]), "+f"(d[2]), "+f"(d[3])
        : "r"(a0), "r"(a1), "r"(a2), "r"(a3), "r"(b0), "r"(b1));
}

__device__ __forceinline__ uint32_t hscale(uint32_t u, __half2 s) {
    __half2 v = *reinterpret_cast<__half2*>(&u);
    v = __hmul2(v, s);
    return *reinterpret_cast<uint32_t*>(&v);
}

// ---------------- K0: zero scratch + fp16 node table + pack W + bias ----------------
__global__ void k_init(const float* __restrict__ node,
                       const float* __restrict__ WO, const float* __restrict__ WI,
                       const float* __restrict__ WS, const float* __restrict__ bO,
                       const float* __restrict__ bI, const float* __restrict__ bS) {
    size_t idx = (size_t)blockIdx.x * blockDim.x + threadIdx.x;
    size_t stride = (size_t)gridDim.x * blockDim.x;
    const size_t n4 = (size_t)N_NODES * 16;
    uint4 z = make_uint4(0, 0, 0, 0);
    uint4* ao = reinterpret_cast<uint4*>(g_acc_o);
    uint4* ai = reinterpret_cast<uint4*>(g_acc_i);
    for (size_t i = idx; i < n4; i += stride) { ao[i] = z; ai[i] = z; }
    // node fp32 -> fp16 table (float4 loads, uint2 stores)
    const float4* nsrc = reinterpret_cast<const float4*>(node);
    uint2* ndst = reinterpret_cast<uint2*>(g_node16);
    const size_t nq = (size_t)N_NODES * 32;
    for (size_t i = idx; i < nq; i += stride) {
        float4 v = __ldg(&nsrc[i]);
        __half2 a = __floats2half2_rn(v.x, v.y);
        __half2 b = __floats2half2_rn(v.z, v.w);
        ndst[i] = make_uint2(*reinterpret_cast<uint32_t*>(&a),
                             *reinterpret_cast<uint32_t*>(&b));
    }
    float4 zf = make_float4(0.f, 0.f, 0.f, 0.f);
    float4* cp = reinterpret_cast<float4*>(g_cnt);
    for (size_t i = idx; i < (2 * N_NODES) / 4; i += stride) cp[i] = zf;
    if (idx < D) { g_sum[idx] = 0.0; g_sumsq[idx] = 0.0; g_bias[idx] = bO[idx] + bI[idx] + bS[idx]; }
    if (idx < 24 * 16 * 32) {
        int t  = (int)idx >> 9;
        int nt = ((int)idx >> 5) & 15;
        int l  = (int)idx & 31;
        int n  = nt * 8 + (l >> 2);
        int kg = t * 16 + (l & 3) * 2;
        const float* Wsrc = (kg < 128) ? WO : ((kg < 256) ? WI : WS);
        int kk = kg & 127;
        float w00 = __ldg(&Wsrc[n * 128 + kk]);
        float w01 = __ldg(&Wsrc[n * 128 + kk + 1]);
        float w10 = __ldg(&Wsrc[n * 128 + kk + 8]);
        float w11 = __ldg(&Wsrc[n * 128 + kk + 9]);
        __half2 b0 = __floats2half2_rn(w00, w01);
        __half2 b1 = __floats2half2_rn(w10, w11);
        g_Bfrag[idx] = make_uint2(*reinterpret_cast<uint32_t*>(&b0),
                                  *reinterpret_cast<uint32_t*>(&b1));
    }
}

// ---------------- K1: edge scatter (fp16 node reads, direct edge loads) ----------------
__global__ __launch_bounds__(256) void k_scatter(const float* __restrict__ edge,
                                                 const int* __restrict__ src,
                                                 const int* __restrict__ dst) {
    int e = blockIdx.x * 8 + (threadIdx.x >> 5);
    if (e >= N_EDGES) return;
    int lane = threadIdx.x & 31;
    int half = lane >> 4;
    int i = lane & 15;
    int s = __ldg(&src[e]);
    int d = __ldg(&dst[e]);
    const float4* ep = reinterpret_cast<const float4*>(edge) + (size_t)e * 32;
    float4 eA = __ldcs(&ep[2 * i]);
    float4 eB = __ldcs(&ep[2 * i + 1]);
    int nrow = half ? d : s;
    const uint4* n16 = reinterpret_cast<const uint4*>(g_node16);
    uint4 nv = __ldg(&n16[(size_t)nrow * 16 + i]);   // elements 8i..8i+7 as 4x half2
    float2 f0 = __half22float2(*reinterpret_cast<__half2*>(&nv.x));
    float2 f1 = __half22float2(*reinterpret_cast<__half2*>(&nv.y));
    float2 f2 = __half22float2(*reinterpret_cast<__half2*>(&nv.z));
    float2 f3 = __half22float2(*reinterpret_cast<__half2*>(&nv.w));
    __half2 m0 = __floats2half2_rn(f0.x - eA.x, f0.y - eA.y);
    __half2 m1 = __floats2half2_rn(f1.x - eA.z, f1.y - eA.w);
    __half2 m2 = __floats2half2_rn(f2.x - eB.x, f2.y - eB.y);
    __half2 m3 = __floats2half2_rn(f3.x - eB.z, f3.y - eB.w);
    __half2* base = half ? (g_acc_i + (size_t)s * 64) : (g_acc_o + (size_t)d * 64);
    red_add_h2v4(base + i * 4, m0, m1, m2, m3);
    if (lane == 0)  atomicAdd(&g_cnt[d], 1.f);
    if (lane == 16) atomicAdd(&g_cnt[N_NODES + s], 1.f);
}

// ---------------- K2: fp16 HMMA GEMM, 2-kstep cp.async stages ----------------
// CTA: 128 rows x 128 cols, 8 warps = 4 (rows, wy) x 2 (cols, wx), warp tile 32x64.
#define NSTAGE 4
#define ROW_B 80                       // 64B data + 16B pad (conflict-free ldmatrix)
#define STG_BYTES (128 * ROW_B)

__global__ __launch_bounds__(256, 2) void k_gemm(float* __restrict__ out) {
    __shared__ __align__(16) unsigned char sA[NSTAGE][STG_BYTES];
    __shared__ float s_inv[2 * 128];
    __shared__ float s_red[2 * 128];

    int tid = threadIdx.x;
    int l = tid & 31;
    int w = tid >> 5;
    int wy = w & 3;           // row group
    int wx = w >> 2;          // col group
    int row0 = blockIdx.x * 128;

    uint32_t sA_base = (uint32_t)__cvta_generic_to_shared(&sA[0][0]);

    {
        int i = tid & 127;
        int r = row0 + i;
        float v = 0.f;
        if (r < N_NODES) v = 1.f / fmaxf(g_cnt[(tid < 128 ? 0 : N_NODES) + r], 1.f);
        s_inv[tid] = v;
        if (tid < 128) { s_red[tid] = 0.f; s_red[128 + tid] = 0.f; }
    }

    int crow = tid >> 1;
    int chalf = tid & 1;
    int cgrow = row0 + crow;
    int cvalid = (cgrow < N_NODES) ? 16 : 0;
    uint32_t cdst = crow * ROW_B + chalf * 32;

#define ISSUE_STAGE(st)                                                                  \
    do {                                                                                 \
        if ((st) < 12) {                                                                 \
            const char* _b = ((st) < 4) ? (const char*)g_acc_o                           \
                           : ((st) < 8) ? (const char*)g_acc_i : (const char*)g_node16;  \
            const char* _g = _b + (size_t)cgrow * 256 + ((st) & 3) * 64 + chalf * 32;    \
            uint32_t _s = sA_base + ((st) & (NSTAGE - 1)) * STG_BYTES + cdst;            \
            asm volatile("cp.async.cg.shared.global [%0], [%1], 16, %2;"                 \
                         :: "r"(_s), "l"(_g), "r"(cvalid));                              \
            asm volatile("cp.async.cg.shared.global [%0], [%1], 16, %2;"                 \
                         :: "r"(_s + 16), "l"(_g + 16), "r"(cvalid));                    \
        }                                                                                \
        asm volatile("cp.async.commit_group;");                                          \
    } while (0)

    ISSUE_STAGE(0);
    ISSUE_STAGE(1);
    ISSUE_STAGE(2);
    __syncthreads();   // s_inv/s_red ready

    float acc[2][8][4];
#pragma unroll
    for (int mt = 0; mt < 2; mt++)
#pragma unroll
        for (int nt = 0; nt < 8; nt++)
#pragma unroll
            for (int q = 0; q < 4; q++) acc[mt][nt][q] = 0.f;

    const int lq = l >> 2;
    const int lk = (l & 3) * 2;

    __half2 sco[2][2], sci[2][2];
#pragma unroll
    for (int mt = 0; mt < 2; mt++) {
        int rbase = wy * 32 + mt * 16 + lq;
        sco[mt][0] = __float2half2_rn(s_inv[rbase]);
        sco[mt][1] = __float2half2_rn(s_inv[rbase + 8]);
        sci[mt][0] = __float2half2_rn(s_inv[128 + rbase]);
        sci[mt][1] = __float2half2_rn(s_inv[128 + rbase + 8]);
    }

    for (int st = 0; st < 12; st++) {
        asm volatile("cp.async.wait_group %0;" :: "n"(2));
        __syncthreads();

        uint32_t stg = sA_base + (st & (NSTAGE - 1)) * STG_BYTES;
        uint32_t A[2][2][4];    // [sub][mt][frag]
#pragma unroll
        for (int sub = 0; sub < 2; sub++) {
#pragma unroll
            for (int mt = 0; mt < 2; mt++) {
                int trow = wy * 32 + mt * 16 + (l & 15);
                uint32_t addr = stg + trow * ROW_B + sub * 32 + (l >> 4) * 16;
                asm volatile("ldmatrix.sync.aligned.m8n8.x4.shared.b16 {%0,%1,%2,%3}, [%4];"
                             : "=r"(A[sub][mt][0]), "=r"(A[sub][mt][1]),
                               "=r"(A[sub][mt][2]), "=r"(A[sub][mt][3])
                             : "r"(addr));
                if (st < 8) {
                    const __half2* sc = (st < 4) ? sco[mt] : sci[mt];
                    A[sub][mt][0] = hscale(A[sub][mt][0], sc[0]);
                    A[sub][mt][1] = hscale(A[sub][mt][1], sc[1]);
                    A[sub][mt][2] = hscale(A[sub][mt][2], sc[0]);
                    A[sub][mt][3] = hscale(A[sub][mt][3], sc[1]);
                }
            }
        }
        ISSUE_STAGE(st + 3);

#pragma unroll
        for (int sub = 0; sub < 2; sub++) {
            int t = st * 2 + sub;
            const uint2* gBt = g_Bfrag + (t * 16 + wx * 8) * 32 + l;
#pragma unroll
            for (int nt = 0; nt < 8; nt++) {
                uint2 B = __ldg(&gBt[nt * 32]);
#pragma unroll
                for (int mt = 0; mt < 2; mt++) {
                    mma_fp16(acc[mt][nt], A[sub][mt][0], A[sub][mt][1],
                             A[sub][mt][2], A[sub][mt][3], B.x, B.y);
                }
            }
        }
    }

    // ---- epilogue: h = (acc + bias)/3, store, BN partial stats ----
    const float third = 1.f / 3.f;
    const float2* bias2 = reinterpret_cast<const float2*>(g_bias);
    float2* o2 = reinterpret_cast<float2*>(out);
    float ps[16], pq[16];
#pragma unroll
    for (int j = 0; j < 16; j++) { ps[j] = 0.f; pq[j] = 0.f; }

#pragma unroll
    for (int mt = 0; mt < 2; mt++) {
        int ra = row0 + wy * 32 + mt * 16 + lq;
        int rb = ra + 8;
#pragma unroll
        for (int nt = 0; nt < 8; nt++) {
            int col = wx * 64 + nt * 8 + lk;
            float2 bv = __ldg(&bias2[col >> 1]);
            if (ra < N_NODES) {
                float2 h0;
                h0.x = (acc[mt][nt][0] + bv.x) * third;
                h0.y = (acc[mt][nt][1] + bv.y) * third;
                o2[(size_t)ra * 64 + (col >> 1)] = h0;
                ps[nt * 2 + 0] += h0.x; pq[nt * 2 + 0] += h0.x * h0.x;
                ps[nt * 2 + 1] += h0.y; pq[nt * 2 + 1] += h0.y * h0.y;
            }
            if (rb < N_NODES) {
                float2 h1;
                h1.x = (acc[mt][nt][2] + bv.x) * third;
                h1.y = (acc[mt][nt][3] + bv.y) * third;
                o2[(size_t)rb * 64 + (col >> 1)] = h1;
                ps[nt * 2 + 0] += h1.x; pq[nt * 2 + 0] += h1.x * h1.x;
                ps[nt * 2 + 1] += h1.y; pq[nt * 2 + 1] += h1.y * h1.y;
            }
        }
    }
#pragma unroll
    for (int j = 0; j < 16; j++) {
        ps[j] += __shfl_xor_sync(0xFFFFFFFFu, ps[j], 4);
        ps[j] += __shfl_xor_sync(0xFFFFFFFFu, ps[j], 8);
        ps[j] += __shfl_xor_sync(0xFFFFFFFFu, ps[j], 16);
        pq[j] += __shfl_xor_sync(0xFFFFFFFFu, pq[j], 4);
        pq[j] += __shfl_xor_sync(0xFFFFFFFFu, pq[j], 8);
        pq[j] += __shfl_xor_sync(0xFFFFFFFFu, pq[j], 16);
    }
    if (l < 4) {
#pragma unroll
        for (int j = 0; j < 16; j++) {
            int col = wx * 64 + (j >> 1) * 8 + l * 2 + (j & 1);
            atomicAdd(&s_red[col], ps[j]);
            atomicAdd(&s_red[128 + col], pq[j]);
        }
    }
    __syncthreads();
    if (tid < 128) atomicAdd(&g_sum[tid], (double)s_red[tid]);
    else           atomicAdd(&g_sumsq[tid - 128], (double)s_red[tid]);
}

// ---------------- K3: BN finalize + in-place normalize (fused, hoisted scales) ----------------
// grid MUST be 2048 x 256: stride = 524288 float4 == 0 mod 32 -> per-thread column fixed.
#define BN_GRID 2048

__global__ __launch_bounds__(256) void k_bn(float* __restrict__ out,
                                            const float* __restrict__ gamma,
                                            const float* __restrict__ beta) {
    __shared__ float s_aff[2 * D];
    int tid = threadIdx.x;
    if (tid < D) {
        double mu = g_sum[tid] / (double)N_NODES;
        double var = g_sumsq[tid] / (double)N_NODES - mu * mu;
        float sc = __ldg(&gamma[tid]) * rsqrtf((float)var + BN_EPS);
        s_aff[tid] = sc;
        s_aff[D + tid] = __ldg(&beta[tid]) - (float)mu * sc;
    }
    __syncthreads();
    size_t idx = (size_t)blockIdx.x * 256 + tid;
    const size_t stride = (size_t)BN_GRID * 256;   // multiple of 32
    const size_t n4 = (size_t)N_NODES * D / 4;
    float4* o4 = reinterpret_cast<float4*>(out);
    // column group is invariant across the whole loop -> hoist
    float4 sc = reinterpret_cast<const float4*>(s_aff)[idx & 31];
    float4 sh = reinterpret_cast<const float4*>(s_aff + D)[idx & 31];
    for (size_t i = idx; i < n4; i += stride) {
        float4 v = o4[i];
        v.x = fmaf(v.x, sc.x, sh.x);
        v.y = fmaf(v.y, sc.y, sh.y);
        v.z = fmaf(v.z, sc.z, sh.z);
        v.w = fmaf(v.w, sc.w, sh.w);
        o4[i] = v;
    }
}

// ---------------- launch ----------------
extern "C" void kernel_launch(void* const* d_in, const int* in_sizes, int n_in,
                              void* d_out, int out_size) {
    const float* node  = (const float*)d_in[0];
    const float* edge  = (const float*)d_in[1];
    const float* WO    = (const float*)d_in[2];
    const float* bO    = (const float*)d_in[3];
    const float* WI    = (const float*)d_in[4];
    const float* bI    = (const float*)d_in[5];
    const float* WS    = (const float*)d_in[6];
    const float* bS    = (const float*)d_in[7];
    const float* gamma = (const float*)d_in[8];
    const float* beta  = (const float*)d_in[9];
    const int*   src   = (const int*)d_in[10];
    const int*   dst   = (const int*)d_in[11];
    float* out = (float*)d_out;

    k_init<<<1184, 256>>>(node, WO, WI, WS, bO, bI, bS);
    k_scatter<<<N_EDGES / 8, 256>>>(edge, src, dst);
    k_gemm<<<(N_NODES + 127) / 128, 256>>>(out);
    k_bn<<<BN_GRID, 256>>>(out, gamma, beta);
}

// round 14
// speedup vs baseline: 1.0985x; 1.0316x over previous
#include <cuda_runtime.h>
#include <cuda_bf16.h>
#include <cuda_fp16.h>
#include <cstdint>
#include <cstddef>

#define N_NODES 100000
#define N_EDGES 600000
#define D 128
#define BN_EPS 1e-5f

// ---------------- scratch (static device globals; no allocation) ----------------
__device__ __half2 g_acc_o[(size_t)N_NODES * 64];   // fp16 sums of (h_src - e) at dst
__device__ __half2 g_acc_i[(size_t)N_NODES * 64];   // fp16 sums of (h_dst - e) at src
__device__ __half2 g_node16[(size_t)N_NODES * 64];  // fp16 copy of node_embs
__device__ float  g_cnt[2 * N_NODES];               // [0:N) in-deg(dst), [N:2N) deg at src
// B fragments (fp16, paired n-tiles): [kstep 0..23][ntpair 0..7][lane 0..31]
//   uint4 = (b0 of ntile 2p, b1 of ntile 2p, b0 of ntile 2p+1, b1 of ntile 2p+1)
__device__ uint4  g_Bfrag[24 * 8 * 32];
__device__ float  g_bias[D];
__device__ double g_sum[D];
__device__ double g_sumsq[D];

// ---------------- helpers ----------------
__device__ __forceinline__ void red_add_h2v4(__half2* p, __half2 a, __half2 b,
                                             __half2 c, __half2 d) {
    asm volatile("red.global.add.noftz.v4.f16x2 [%0], {%1,%2,%3,%4};"
                 :: "l"(p),
                    "r"(*reinterpret_cast<uint32_t*>(&a)),
                    "r"(*reinterpret_cast<uint32_t*>(&b)),
                    "r"(*reinterpret_cast<uint32_t*>(&c)),
                    "r"(*reinterpret_cast<uint32_t*>(&d)) : "memory");
}

__device__ __forceinline__ void mma_fp16(float* d, uint32_t a0, uint32_t a1, uint32_t a2,
                                         uint32_t a3, uint32_t b0, uint32_t b1) {
    asm volatile(
        "mma.sync.aligned.m16n8k16.row.col.f32.f16.f16.f32 "
        "{%0,%1,%2,%3}, {%4,%5,%6,%7}, {%8,%9}, {%0,%1,%2,%3};"
        : "+f"(d[0]), "+f"(d[1]), "+f"(d[2]), "+f"(d[3])
        : "r"(a0), "r"(a1), "r"(a2), "r"(a3), "r"(b0), "r"(b1));
}

__device__ __forceinline__ uint32_t hscale(uint32_t u, __half2 s) {
    __half2 v = *reinterpret_cast<__half2*>(&u);
    v = __hmul2(v, s);
    return *reinterpret_cast<uint32_t*>(&v);
}

// ---------------- K0: zero scratch + fp16 node table + pack W + bias ----------------
__global__ void k_init(const float* __restrict__ node,
                       const float* __restrict__ WO, const float* __restrict__ WI,
                       const float* __restrict__ WS, const float* __restrict__ bO,
                       const float* __restrict__ bI, const float* __restrict__ bS) {
    size_t idx = (size_t)blockIdx.x * blockDim.x + threadIdx.x;
    size_t stride = (size_t)gridDim.x * blockDim.x;
    const size_t n4 = (size_t)N_NODES * 16;
    uint4 z = make_uint4(0, 0, 0, 0);
    uint4* ao = reinterpret_cast<uint4*>(g_acc_o);
    uint4* ai = reinterpret_cast<uint4*>(g_acc_i);
    for (size_t i = idx; i < n4; i += stride) { ao[i] = z; ai[i] = z; }
    // node fp32 -> fp16 table (float4 loads, uint2 stores)
    const float4* nsrc = reinterpret_cast<const float4*>(node);
    uint2* ndst = reinterpret_cast<uint2*>(g_node16);
    const size_t nq = (size_t)N_NODES * 32;
    for (size_t i = idx; i < nq; i += stride) {
        float4 v = __ldg(&nsrc[i]);
        __half2 a = __floats2half2_rn(v.x, v.y);
        __half2 b = __floats2half2_rn(v.z, v.w);
        ndst[i] = make_uint2(*reinterpret_cast<uint32_t*>(&a),
                             *reinterpret_cast<uint32_t*>(&b));
    }
    float4 zf = make_float4(0.f, 0.f, 0.f, 0.f);
    float4* cp = reinterpret_cast<float4*>(g_cnt);
    for (size_t i = idx; i < (2 * N_NODES) / 4; i += stride) cp[i] = zf;
    if (idx < D) { g_sum[idx] = 0.0; g_sumsq[idx] = 0.0; g_bias[idx] = bO[idx] + bI[idx] + bS[idx]; }
    if (idx < 24 * 8 * 32) {
        int t  = (int)idx >> 8;           // kstep 0..23
        int np = ((int)idx >> 5) & 7;     // ntile pair 0..7 (global ntiles 2np, 2np+1)
        int l  = (int)idx & 31;
        int kg = t * 16 + (l & 3) * 2;
        const float* Wsrc = (kg < 128) ? WO : ((kg < 256) ? WI : WS);
        int kk = kg & 127;
        int n0 = (np * 2) * 8 + (l >> 2);
        int n1 = n0 + 8;
        float a00 = __ldg(&Wsrc[n0 * 128 + kk]);
        float a01 = __ldg(&Wsrc[n0 * 128 + kk + 1]);
        float a10 = __ldg(&Wsrc[n0 * 128 + kk + 8]);
        float a11 = __ldg(&Wsrc[n0 * 128 + kk + 9]);
        float c00 = __ldg(&Wsrc[n1 * 128 + kk]);
        float c01 = __ldg(&Wsrc[n1 * 128 + kk + 1]);
        float c10 = __ldg(&Wsrc[n1 * 128 + kk + 8]);
        float c11 = __ldg(&Wsrc[n1 * 128 + kk + 9]);
        __half2 b0 = __floats2half2_rn(a00, a01);
        __half2 b1 = __floats2half2_rn(a10, a11);
        __half2 b2 = __floats2half2_rn(c00, c01);
        __half2 b3 = __floats2half2_rn(c10, c11);
        g_Bfrag[idx] = make_uint4(*reinterpret_cast<uint32_t*>(&b0),
                                  *reinterpret_cast<uint32_t*>(&b1),
                                  *reinterpret_cast<uint32_t*>(&b2),
                                  *reinterpret_cast<uint32_t*>(&b3));
    }
}

// ---------------- K1: edge scatter (fp16 node reads, direct edge loads) ----------------
__global__ __launch_bounds__(256) void k_scatter(const float* __restrict__ edge,
                                                 const int* __restrict__ src,
                                                 const int* __restrict__ dst) {
    int e = blockIdx.x * 8 + (threadIdx.x >> 5);
    if (e >= N_EDGES) return;
    int lane = threadIdx.x & 31;
    int half = lane >> 4;
    int i = lane & 15;
    int s = __ldg(&src[e]);
    int d = __ldg(&dst[e]);
    const float4* ep = reinterpret_cast<const float4*>(edge) + (size_t)e * 32;
    float4 eA = __ldcs(&ep[2 * i]);
    float4 eB = __ldcs(&ep[2 * i + 1]);
    int nrow = half ? d : s;
    const uint4* n16 = reinterpret_cast<const uint4*>(g_node16);
    uint4 nv = __ldg(&n16[(size_t)nrow * 16 + i]);   // elements 8i..8i+7 as 4x half2
    float2 f0 = __half22float2(*reinterpret_cast<__half2*>(&nv.x));
    float2 f1 = __half22float2(*reinterpret_cast<__half2*>(&nv.y));
    float2 f2 = __half22float2(*reinterpret_cast<__half2*>(&nv.z));
    float2 f3 = __half22float2(*reinterpret_cast<__half2*>(&nv.w));
    __half2 m0 = __floats2half2_rn(f0.x - eA.x, f0.y - eA.y);
    __half2 m1 = __floats2half2_rn(f1.x - eA.z, f1.y - eA.w);
    __half2 m2 = __floats2half2_rn(f2.x - eB.x, f2.y - eB.y);
    __half2 m3 = __floats2half2_rn(f3.x - eB.z, f3.y - eB.w);
    __half2* base = half ? (g_acc_i + (size_t)s * 64) : (g_acc_o + (size_t)d * 64);
    red_add_h2v4(base + i * 4, m0, m1, m2, m3);
    if (lane == 0)  atomicAdd(&g_cnt[d], 1.f);
    if (lane == 16) atomicAdd(&g_cnt[N_NODES + s], 1.f);
}

// ---------------- K2: fp16 HMMA GEMM, 2-kstep cp.async stages, 6-deep pipeline ----------------
// CTA: 128 rows x 128 cols, 8 warps = 4 (rows, wy) x 2 (cols, wx), warp tile 32x64.
#define NSTAGE 6
#define ROW_B 80                       // 64B data + 16B pad (conflict-free ldmatrix)
#define STG_BYTES (128 * ROW_B)
#define GEMM_SMEM (NSTAGE * STG_BYTES)

__global__ __launch_bounds__(256, 2) void k_gemm(float* __restrict__ out) {
    extern __shared__ __align__(16) unsigned char sA[];
    __shared__ float s_inv[2 * 128];
    __shared__ float s_red[2 * 128];

    int tid = threadIdx.x;
    int l = tid & 31;
    int w = tid >> 5;
    int wy = w & 3;           // row group
    int wx = w >> 2;          // col group
    int row0 = blockIdx.x * 128;

    uint32_t sA_base = (uint32_t)__cvta_generic_to_shared(sA);

    {
        int i = tid & 127;
        int r = row0 + i;
        float v = 0.f;
        if (r < N_NODES) v = 1.f / fmaxf(g_cnt[(tid < 128 ? 0 : N_NODES) + r], 1.f);
        s_inv[tid] = v;
        if (tid < 128) { s_red[tid] = 0.f; s_red[128 + tid] = 0.f; }
    }

    int crow = tid >> 1;
    int chalf = tid & 1;
    int cgrow = row0 + crow;
    int cvalid = (cgrow < N_NODES) ? 16 : 0;
    uint32_t cdst = crow * ROW_B + chalf * 32;

#define ISSUE_STAGE(st)                                                                  \
    do {                                                                                 \
        if ((st) < 12) {                                                                 \
            const char* _b = ((st) < 4) ? (const char*)g_acc_o                           \
                           : ((st) < 8) ? (const char*)g_acc_i : (const char*)g_node16;  \
            const char* _g = _b + (size_t)cgrow * 256 + ((st) & 3) * 64 + chalf * 32;    \
            uint32_t _s = sA_base + ((st) % NSTAGE) * STG_BYTES + cdst;                  \
            asm volatile("cp.async.cg.shared.global [%0], [%1], 16, %2;"                 \
                         :: "r"(_s), "l"(_g), "r"(cvalid));                              \
            asm volatile("cp.async.cg.shared.global [%0], [%1], 16, %2;"                 \
                         :: "r"(_s + 16), "l"(_g + 16), "r"(cvalid));                    \
        }                                                                                \
        asm volatile("cp.async.commit_group;");                                          \
    } while (0)

    ISSUE_STAGE(0);
    ISSUE_STAGE(1);
    ISSUE_STAGE(2);
    ISSUE_STAGE(3);
    ISSUE_STAGE(4);
    __syncthreads();   // s_inv/s_red ready

    float acc[2][8][4];
#pragma unroll
    for (int mt = 0; mt < 2; mt++)
#pragma unroll
        for (int nt = 0; nt < 8; nt++)
#pragma unroll
            for (int q = 0; q < 4; q++) acc[mt][nt][q] = 0.f;

    const int lq = l >> 2;
    const int lk = (l & 3) * 2;

    __half2 sco[2][2], sci[2][2];
#pragma unroll
    for (int mt = 0; mt < 2; mt++) {
        int rbase = wy * 32 + mt * 16 + lq;
        sco[mt][0] = __float2half2_rn(s_inv[rbase]);
        sco[mt][1] = __float2half2_rn(s_inv[rbase + 8]);
        sci[mt][0] = __float2half2_rn(s_inv[128 + rbase]);
        sci[mt][1] = __float2half2_rn(s_inv[128 + rbase + 8]);
    }

    for (int st = 0; st < 12; st++) {
        asm volatile("cp.async.wait_group %0;" :: "n"(4));
        __syncthreads();

        uint32_t stg = sA_base + (st % NSTAGE) * STG_BYTES;
        uint32_t A[2][2][4];    // [sub][mt][frag]
#pragma unroll
        for (int sub = 0; sub < 2; sub++) {
#pragma unroll
            for (int mt = 0; mt < 2; mt++) {
                int trow = wy * 32 + mt * 16 + (l & 15);
                uint32_t addr = stg + trow * ROW_B + sub * 32 + (l >> 4) * 16;
                asm volatile("ldmatrix.sync.aligned.m8n8.x4.shared.b16 {%0,%1,%2,%3}, [%4];"
                             : "=r"(A[sub][mt][0]), "=r"(A[sub][mt][1]),
                               "=r"(A[sub][mt][2]), "=r"(A[sub][mt][3])
                             : "r"(addr));
                if (st < 8) {
                    const __half2* sc = (st < 4) ? sco[mt] : sci[mt];
                    A[sub][mt][0] = hscale(A[sub][mt][0], sc[0]);
                    A[sub][mt][1] = hscale(A[sub][mt][1], sc[1]);
                    A[sub][mt][2] = hscale(A[sub][mt][2], sc[0]);
                    A[sub][mt][3] = hscale(A[sub][mt][3], sc[1]);
                }
            }
        }
        ISSUE_STAGE(st + 5);

#pragma unroll
        for (int sub = 0; sub < 2; sub++) {
            int t = st * 2 + sub;
            const uint4* gBt = g_Bfrag + (t * 8 + wx * 4) * 32 + l;
#pragma unroll
            for (int np = 0; np < 4; np++) {
                uint4 B = __ldg(&gBt[np * 32]);
#pragma unroll
                for (int mt = 0; mt < 2; mt++) {
                    mma_fp16(acc[mt][np * 2], A[sub][mt][0], A[sub][mt][1],
                             A[sub][mt][2], A[sub][mt][3], B.x, B.y);
                    mma_fp16(acc[mt][np * 2 + 1], A[sub][mt][0], A[sub][mt][1],
                             A[sub][mt][2], A[sub][mt][3], B.z, B.w);
                }
            }
        }
    }

    // ---- epilogue: h = (acc + bias)/3, store, BN partial stats ----
    const float third = 1.f / 3.f;
    const float2* bias2 = reinterpret_cast<const float2*>(g_bias);
    float2* o2 = reinterpret_cast<float2*>(out);
    float ps[16], pq[16];
#pragma unroll
    for (int j = 0; j < 16; j++) { ps[j] = 0.f; pq[j] = 0.f; }

#pragma unroll
    for (int mt = 0; mt < 2; mt++) {
        int ra = row0 + wy * 32 + mt * 16 + lq;
        int rb = ra + 8;
#pragma unroll
        for (int nt = 0; nt < 8; nt++) {
            int col = wx * 64 + nt * 8 + lk;
            float2 bv = __ldg(&bias2[col >> 1]);
            if (ra < N_NODES) {
                float2 h0;
                h0.x = (acc[mt][nt][0] + bv.x) * third;
                h0.y = (acc[mt][nt][1] + bv.y) * third;
                o2[(size_t)ra * 64 + (col >> 1)] = h0;
                ps[nt * 2 + 0] += h0.x; pq[nt * 2 + 0] += h0.x * h0.x;
                ps[nt * 2 + 1] += h0.y; pq[nt * 2 + 1] += h0.y * h0.y;
            }
            if (rb < N_NODES) {
                float2 h1;
                h1.x = (acc[mt][nt][2] + bv.x) * third;
                h1.y = (acc[mt][nt][3] + bv.y) * third;
                o2[(size_t)rb * 64 + (col >> 1)] = h1;
                ps[nt * 2 + 0] += h1.x; pq[nt * 2 + 0] += h1.x * h1.x;
                ps[nt * 2 + 1] += h1.y; pq[nt * 2 + 1] += h1.y * h1.y;
            }
        }
    }
#pragma unroll
    for (int j = 0; j < 16; j++) {
        ps[j] += __shfl_xor_sync(0xFFFFFFFFu, ps[j], 4);
        ps[j] += __shfl_xor_sync(0xFFFFFFFFu, ps[j], 8);
        ps[j] += __shfl_xor_sync(0xFFFFFFFFu, ps[j], 16);
        pq[j] += __shfl_xor_sync(0xFFFFFFFFu, pq[j], 4);
        pq[j] += __shfl_xor_sync(0xFFFFFFFFu, pq[j], 8);
        pq[j] += __shfl_xor_sync(0xFFFFFFFFu, pq[j], 16);
    }
    if (l < 4) {
#pragma unroll
        for (int j = 0; j < 16; j++) {
            int col = wx * 64 + (j >> 1) * 8 + l * 2 + (j & 1);
            atomicAdd(&s_red[col], ps[j]);
            atomicAdd(&s_red[128 + col], pq[j]);
        }
    }
    __syncthreads();
    if (tid < 128) atomicAdd(&g_sum[tid], (double)s_red[tid]);
    else           atomicAdd(&g_sumsq[tid - 128], (double)s_red[tid]);
}

// ---------------- K3: BN finalize + in-place normalize (fused, 2-stream ILP) ----------------
// grid MUST be 2048 x 256: stride = 524288 float4 == 0 mod 32; 1.6M == 0 mod 32.
#define BN_GRID 2048
#define BN_HALF 1600000u

__global__ __launch_bounds__(256) void k_bn(float* __restrict__ out,
                                            const float* __restrict__ gamma,
                                            const float* __restrict__ beta) {
    __shared__ float s_aff[2 * D];
    int tid = threadIdx.x;
    if (tid < D) {
        double mu = g_sum[tid] / (double)N_NODES;
        double var = g_sumsq[tid] / (double)N_NODES - mu * mu;
        float sc = __ldg(&gamma[tid]) * rsqrtf((float)var + BN_EPS);
        s_aff[tid] = sc;
        s_aff[D + tid] = __ldg(&beta[tid]) - (float)mu * sc;
    }
    __syncthreads();
    size_t idx = (size_t)blockIdx.x * 256 + tid;
    const size_t stride = (size_t)BN_GRID * 256;   // multiple of 32
    float4* o4 = reinterpret_cast<float4*>(out);
    float4 sc = reinterpret_cast<const float4*>(s_aff)[idx & 31];
    float4 sh = reinterpret_cast<const float4*>(s_aff + D)[idx & 31];
    for (size_t i = idx; i < BN_HALF; i += stride) {
        float4 v0 = o4[i];
        float4 v1 = o4[i + BN_HALF];
        v0.x = fmaf(v0.x, sc.x, sh.x);
        v0.y = fmaf(v0.y, sc.y, sh.y);
        v0.z = fmaf(v0.z, sc.z, sh.z);
        v0.w = fmaf(v0.w, sc.w, sh.w);
        v1.x = fmaf(v1.x, sc.x, sh.x);
        v1.y = fmaf(v1.y, sc.y, sh.y);
        v1.z = fmaf(v1.z, sc.z, sh.z);
        v1.w = fmaf(v1.w, sc.w, sh.w);
        o4[i] = v0;
        o4[i + BN_HALF] = v1;
    }
}

// ---------------- launch ----------------
extern "C" void kernel_launch(void* const* d_in, const int* in_sizes, int n_in,
                              void* d_out, int out_size) {
    const float* node  = (const float*)d_in[0];
    const float* edge  = (const float*)d_in[1];
    const float* WO    = (const float*)d_in[2];
    const float* bO    = (const float*)d_in[3];
    const float* WI    = (const float*)d_in[4];
    const float* bI    = (const float*)d_in[5];
    const float* WS    = (const float*)d_in[6];
    const float* bS    = (const float*)d_in[7];
    const float* gamma = (const float*)d_in[8];
    const float* beta  = (const float*)d_in[9];
    const int*   src   = (const int*)d_in[10];
    const int*   dst   = (const int*)d_in[11];
    float* out = (float*)d_out;

    cudaFuncSetAttribute(k_gemm, cudaFuncAttributeMaxDynamicSharedMemorySize, GEMM_SMEM);

    k_init<<<1184, 256>>>(node, WO, WI, WS, bO, bI, bS);
    k_scatter<<<N_EDGES / 8, 256>>>(edge, src, dst);
    k_gemm<<<(N_NODES + 127) / 128, 256, GEMM_SMEM>>>(out);
    k_bn<<<BN_GRID, 256>>>(out, gamma, beta);
}